// round 3
// baseline (speedup 1.0000x reference)
#include <cuda_runtime.h>

#define NN 100000
#define EE 1200000
#define D  64

// Scratch (device globals: no allocation allowed in kernel_launch)
__device__ float g_q[(size_t)NN * D];
__device__ float g_k[(size_t)NN * D];
__device__ float g_v[(size_t)NN * D];
__device__ float g_skip[(size_t)NN * D];
__device__ float g_logit[EE];
__device__ float g_max[NN];
__device__ float g_sum[NN];

__device__ __forceinline__ void atomicMaxF(float* addr, float val) {
    if (val >= 0.0f) {
        atomicMax((int*)addr, __float_as_int(val));
    } else {
        atomicMin((unsigned int*)addr, __float_as_uint(val));
    }
}

// ---------------------------------------------------------------------------
// K0: init accumulators + zero output
// ---------------------------------------------------------------------------
__global__ void init_kernel(float* __restrict__ out, int n) {
    int total = n * D;
    for (int idx = blockIdx.x * blockDim.x + threadIdx.x; idx < total;
         idx += gridDim.x * blockDim.x) {
        out[idx] = 0.0f;
        if (idx < n) {
            g_max[idx] = __int_as_float(0xff800000);  // -inf
            g_sum[idx] = 0.0f;
        }
    }
}

// ---------------------------------------------------------------------------
// K1: Y[n,64] = X[n,64] @ W[64,64] + B[64]
// Block: 64 rows x 64 cols, 256 threads, each thread 2x8 micro-tile.
// smem: ws 16384B + xs 16640B = 33024B (< 48KB static limit)
// ---------------------------------------------------------------------------
__global__ void __launch_bounds__(256) gemm64(
    const float* __restrict__ X, const float* __restrict__ W,
    const float* __restrict__ B, float* __restrict__ Y, int n) {
    __shared__ float xs[64][D + 1];
    __shared__ float ws[D][D];

    int row0 = blockIdx.x * 64;

    // load W (4096 floats)
    for (int i = threadIdx.x; i < D * D; i += 256)
        ws[i / D][i % D] = W[i];

    // load X tile (float4)
    for (int i = threadIdx.x; i < 64 * (D / 4); i += 256) {
        int r  = i / (D / 4);
        int c4 = i % (D / 4);
        float4 v = make_float4(0.f, 0.f, 0.f, 0.f);
        if (row0 + r < n)
            v = ((const float4*)X)[(size_t)(row0 + r) * (D / 4) + c4];
        xs[r][c4 * 4 + 0] = v.x;
        xs[r][c4 * 4 + 1] = v.y;
        xs[r][c4 * 4 + 2] = v.z;
        xs[r][c4 * 4 + 3] = v.w;
    }
    __syncthreads();

    int tr = (threadIdx.x / 8) * 2;  // 0..62
    int tc = (threadIdx.x % 8) * 8;  // 0..56

    float acc[2][8];
#pragma unroll
    for (int r = 0; r < 2; r++)
#pragma unroll
        for (int c = 0; c < 8; c++) acc[r][c] = 0.0f;

#pragma unroll 8
    for (int kk = 0; kk < D; kk++) {
        float xv[2], wv[8];
#pragma unroll
        for (int r = 0; r < 2; r++) xv[r] = xs[tr + r][kk];
#pragma unroll
        for (int c = 0; c < 8; c++) wv[c] = ws[kk][tc + c];
#pragma unroll
        for (int r = 0; r < 2; r++)
#pragma unroll
            for (int c = 0; c < 8; c++) acc[r][c] = fmaf(xv[r], wv[c], acc[r][c]);
    }

#pragma unroll
    for (int r = 0; r < 2; r++) {
        int grow = row0 + tr + r;
        if (grow < n) {
#pragma unroll
            for (int c = 0; c < 8; c++)
                Y[(size_t)grow * D + tc + c] = acc[r][c] + B[tc + c];
        }
    }
}

// ---------------------------------------------------------------------------
// K2: per-edge logits (warp per edge) + atomic segment max on dst
// edge_index delivered as int32: ei[0..E) = src, ei[E..2E) = dst
// ---------------------------------------------------------------------------
__global__ void __launch_bounds__(256) logits_kernel(
    const int* __restrict__ ei, int E) {
    int warp  = (blockIdx.x * blockDim.x + threadIdx.x) >> 5;
    int lane  = threadIdx.x & 31;
    int nwarp = (gridDim.x * blockDim.x) >> 5;

    for (int e = warp; e < E; e += nwarp) {
        int src = ei[e];
        int dst = ei[E + e];
        float2 a = ((const float2*)(g_q + (size_t)dst * D))[lane];
        float2 b = ((const float2*)(g_k + (size_t)src * D))[lane];
        float d = fmaf(a.x, b.x, a.y * b.y);
#pragma unroll
        for (int o = 16; o > 0; o >>= 1)
            d += __shfl_xor_sync(0xffffffffu, d, o);
        if (lane == 0) {
            d *= 0.125f;  // 1/sqrt(64)
            g_logit[e] = d;
            atomicMaxF(&g_max[dst], d);
        }
    }
}

// ---------------------------------------------------------------------------
// K3: ex = exp(logit - max[dst]); sum[dst] += ex; out[dst] += ex * v[src]
// 16 threads per edge, float4 per thread.
// ---------------------------------------------------------------------------
__global__ void __launch_bounds__(256) agg_kernel(
    const int* __restrict__ ei, float* __restrict__ out, int E) {
    int total = E * 16;
    for (int t = blockIdx.x * blockDim.x + threadIdx.x; t < total;
         t += gridDim.x * blockDim.x) {
        int e    = t >> 4;
        int part = t & 15;
        int src = ei[e];
        int dst = ei[E + e];
        float ex = __expf(g_logit[e] - g_max[dst]);
        if (part == 0) atomicAdd(&g_sum[dst], ex);
        float4 vv = ((const float4*)(g_v + (size_t)src * D))[part];
        float* op = out + (size_t)dst * D + part * 4;
        atomicAdd(op + 0, ex * vv.x);
        atomicAdd(op + 1, ex * vv.y);
        atomicAdd(op + 2, ex * vv.z);
        atomicAdd(op + 3, ex * vv.w);
    }
}

// ---------------------------------------------------------------------------
// K4: out = out / (sum + 1e-16) + skip
// ---------------------------------------------------------------------------
__global__ void __launch_bounds__(256) final_kernel(float* __restrict__ out, int n) {
    int total = n * (D / 4);
    for (int t = blockIdx.x * blockDim.x + threadIdx.x; t < total;
         t += gridDim.x * blockDim.x) {
        int i = t / (D / 4);
        float r = 1.0f / (g_sum[i] + 1e-16f);
        float4 a = ((float4*)out)[t];
        float4 s = ((const float4*)g_skip)[t];
        a.x = fmaf(a.x, r, s.x);
        a.y = fmaf(a.y, r, s.y);
        a.z = fmaf(a.z, r, s.z);
        a.w = fmaf(a.w, r, s.w);
        ((float4*)out)[t] = a;
    }
}

// ---------------------------------------------------------------------------
extern "C" void kernel_launch(void* const* d_in, const int* in_sizes, int n_in,
                              void* d_out, int out_size) {
    const float* x  = (const float*)d_in[0];
    const int*   ei = (const int*)d_in[1];     // int64 in ref -> delivered int32
    // d_in[2] = edge_type (unused by reference)
    const float* Wq = (const float*)d_in[3];
    const float* bq = (const float*)d_in[4];
    const float* Wk = (const float*)d_in[5];
    const float* bk = (const float*)d_in[6];
    const float* Wv = (const float*)d_in[7];
    const float* bv = (const float*)d_in[8];
    const float* Ws = (const float*)d_in[9];
    const float* bs = (const float*)d_in[10];
    float* out = (float*)d_out;

    int n = in_sizes[0] / D;        // 100000
    int E = in_sizes[2];            // 1200000
    if (n > NN) n = NN;
    if (E > EE) E = EE;

    float *gq, *gk, *gv, *gsk;
    cudaGetSymbolAddress((void**)&gq,  g_q);
    cudaGetSymbolAddress((void**)&gk,  g_k);
    cudaGetSymbolAddress((void**)&gv,  g_v);
    cudaGetSymbolAddress((void**)&gsk, g_skip);

    // K0: init
    {
        int total = n * D;
        int blocks = (total + 255) / 256;
        init_kernel<<<blocks, 256>>>(out, n);
    }

    // K1: four GEMMs
    {
        int blocks = (n + 63) / 64;
        gemm64<<<blocks, 256>>>(x, Wq, bq, gq, n);
        gemm64<<<blocks, 256>>>(x, Wk, bk, gk, n);
        gemm64<<<blocks, 256>>>(x, Wv, bv, gv, n);
        gemm64<<<blocks, 256>>>(x, Ws, bs, gsk, n);
    }

    // K2: logits + segment max (warp per edge)
    {
        int warps_per_block = 8;
        int blocks = (E + warps_per_block - 1) / warps_per_block;
        logits_kernel<<<blocks, 256>>>(ei, E);
    }

    // K3: fused exp + segment sum + weighted scatter
    {
        long long total = (long long)E * 16;
        int blocks = (int)((total + 255) / 256);
        agg_kernel<<<blocks, 256>>>(ei, out, E);
    }

    // K4: normalize + skip
    {
        int total = n * (D / 4);
        int blocks = (total + 255) / 256;
        final_kernel<<<blocks, 256>>>(out, n);
    }
}

// round 4
// speedup vs baseline: 2.2466x; 2.2466x over previous
#include <cuda_runtime.h>

#define NN 100000
#define EE 1200000
#define D  64
#define GR 96   // X rows per GEMM block

// Scratch (device globals: no allocation allowed in kernel_launch)
__device__ float g_q[(size_t)NN * D];
__device__ float g_k[(size_t)NN * D];
__device__ float g_v[(size_t)NN * D];
__device__ float g_skip[(size_t)NN * D];
__device__ float g_sum[NN];

// ---------------------------------------------------------------------------
// packed f32x2 helpers (Blackwell sm_100+)
// ---------------------------------------------------------------------------
__device__ __forceinline__ unsigned long long dup_f32x2(float x) {
    unsigned long long r;
    asm("mov.b64 %0, {%1, %1};" : "=l"(r) : "f"(x));
    return r;
}
__device__ __forceinline__ void fma_f32x2(unsigned long long& acc,
                                          unsigned long long a,
                                          unsigned long long b) {
    asm("fma.rn.f32x2 %0, %1, %2, %3;" : "=l"(acc) : "l"(a), "l"(b), "l"(acc));
}
__device__ __forceinline__ float2 unpack_f32x2(unsigned long long p) {
    float lo, hi;
    asm("mov.b64 {%0, %1}, %2;" : "=f"(lo), "=f"(hi) : "l"(p));
    return make_float2(lo, hi);
}

// ---------------------------------------------------------------------------
// K0: zero output + segment sums
// ---------------------------------------------------------------------------
__global__ void init_kernel(float* __restrict__ out, int n) {
    int total = n * D;
    for (int idx = blockIdx.x * blockDim.x + threadIdx.x; idx < total;
         idx += gridDim.x * blockDim.x) {
        out[idx] = 0.0f;
        if (idx < n) g_sum[idx] = 0.0f;
    }
}

// ---------------------------------------------------------------------------
// K1: fused 4-way GEMM: {q,k,v,skip}[n,64] = X[n,64] @ W_i[64,64] + b_i
// X tile staged transposed (xsT[k][row]) so 4-row operand is one LDS.128.
// Per thread: 4 rows x 8 cols via 16 packed fma.f32x2 per k-step.
// smem: xsT 24576B + ws 16384B = 40960B
// ---------------------------------------------------------------------------
__global__ void __launch_bounds__(192) gemm_fused(
    const float* __restrict__ X,
    const float* __restrict__ Wq, const float* __restrict__ bq,
    const float* __restrict__ Wk, const float* __restrict__ bk,
    const float* __restrict__ Wv, const float* __restrict__ bv,
    const float* __restrict__ Ws, const float* __restrict__ bs,
    float* __restrict__ Yq, float* __restrict__ Yk,
    float* __restrict__ Yv, float* __restrict__ Ys, int n) {
    __shared__ float xsT[D][GR];   // [k][row]
    __shared__ float ws[D][D];

    int tid  = threadIdx.x;
    int row0 = blockIdx.x * GR;

    // stage X transposed: consecutive threads -> consecutive rows (conflict-free STS)
    for (int i = tid; i < GR * (D / 4); i += 192) {
        int r  = i % GR;
        int c4 = i / GR;
        float4 v = make_float4(0.f, 0.f, 0.f, 0.f);
        if (row0 + r < n)
            v = ((const float4*)X)[(size_t)(row0 + r) * (D / 4) + c4];
        xsT[c4 * 4 + 0][r] = v.x;
        xsT[c4 * 4 + 1][r] = v.y;
        xsT[c4 * 4 + 2][r] = v.z;
        xsT[c4 * 4 + 3][r] = v.w;
    }

    int tr = (tid >> 3) * 4;  // 0..92
    int tc = (tid & 7) * 8;   // 0..56

    const float* Wm[4] = {Wq, Wk, Wv, Ws};
    const float* Bm[4] = {bq, bk, bv, bs};
    float*       Ym[4] = {Yq, Yk, Yv, Ys};

#pragma unroll 1
    for (int w = 0; w < 4; w++) {
        __syncthreads();  // protect ws from readers of previous iteration
        for (int i = tid; i < D * D / 4; i += 192)
            ((float4*)ws)[i] = ((const float4*)Wm[w])[i];
        __syncthreads();

        unsigned long long acc[4][4];
#pragma unroll
        for (int r = 0; r < 4; r++)
#pragma unroll
            for (int c = 0; c < 4; c++) acc[r][c] = 0ull;

#pragma unroll 8
        for (int kk = 0; kk < D; kk++) {
            float4 xv = *(const float4*)&xsT[kk][tr];
            ulonglong2 wA = *(const ulonglong2*)&ws[kk][tc];
            ulonglong2 wB = *(const ulonglong2*)&ws[kk][tc + 4];
            unsigned long long x0 = dup_f32x2(xv.x);
            unsigned long long x1 = dup_f32x2(xv.y);
            unsigned long long x2 = dup_f32x2(xv.z);
            unsigned long long x3 = dup_f32x2(xv.w);
            fma_f32x2(acc[0][0], x0, wA.x); fma_f32x2(acc[0][1], x0, wA.y);
            fma_f32x2(acc[0][2], x0, wB.x); fma_f32x2(acc[0][3], x0, wB.y);
            fma_f32x2(acc[1][0], x1, wA.x); fma_f32x2(acc[1][1], x1, wA.y);
            fma_f32x2(acc[1][2], x1, wB.x); fma_f32x2(acc[1][3], x1, wB.y);
            fma_f32x2(acc[2][0], x2, wA.x); fma_f32x2(acc[2][1], x2, wA.y);
            fma_f32x2(acc[2][2], x2, wB.x); fma_f32x2(acc[2][3], x2, wB.y);
            fma_f32x2(acc[3][0], x3, wA.x); fma_f32x2(acc[3][1], x3, wA.y);
            fma_f32x2(acc[3][2], x3, wB.x); fma_f32x2(acc[3][3], x3, wB.y);
        }

        float4 bA = ((const float4*)Bm[w])[tc / 4];
        float4 bB = ((const float4*)Bm[w])[tc / 4 + 1];
        float* Y  = Ym[w];
#pragma unroll
        for (int r = 0; r < 4; r++) {
            int grow = row0 + tr + r;
            if (grow < n) {
                float2 p0 = unpack_f32x2(acc[r][0]);
                float2 p1 = unpack_f32x2(acc[r][1]);
                float2 p2 = unpack_f32x2(acc[r][2]);
                float2 p3 = unpack_f32x2(acc[r][3]);
                float4 o0 = make_float4(p0.x + bA.x, p0.y + bA.y,
                                        p1.x + bA.z, p1.y + bA.w);
                float4 o1 = make_float4(p2.x + bB.x, p2.y + bB.y,
                                        p3.x + bB.z, p3.y + bB.w);
                ((float4*)(Y + (size_t)grow * D + tc))[0] = o0;
                ((float4*)(Y + (size_t)grow * D + tc))[1] = o1;
            }
        }
    }
}

// ---------------------------------------------------------------------------
// K2: fused edge pass. 16 threads per edge.
//   d  = (q[dst] . k[src]) / 8          (softmax shift-invariance: no max pass)
//   ex = exp(d)
//   out[dst] += ex * v[src]   (red.global.add.v4.f32)
//   sum[dst] += ex
// ---------------------------------------------------------------------------
__global__ void __launch_bounds__(256) edge_kernel(
    const int* __restrict__ ei, float* __restrict__ out, int E) {
    int gt   = blockIdx.x * blockDim.x + threadIdx.x;
    int e    = gt >> 4;
    int lane = gt & 15;
    if (e >= E) return;

    int src = ei[e];
    int dst = ei[E + e];

    float4 a = ((const float4*)(g_q + (size_t)dst * D))[lane];
    float4 b = ((const float4*)(g_k + (size_t)src * D))[lane];
    float d = fmaf(a.x, b.x, fmaf(a.y, b.y, fmaf(a.z, b.z, a.w * b.w)));
#pragma unroll
    for (int o = 8; o > 0; o >>= 1)
        d += __shfl_xor_sync(0xffffffffu, d, o);

    float ex = __expf(d * 0.125f);

    float4 vv = ((const float4*)(g_v + (size_t)src * D))[lane];
    float* op = out + (size_t)dst * D + lane * 4;
    asm volatile("red.global.add.v4.f32 [%0], {%1, %2, %3, %4};"
                 :: "l"(op), "f"(ex * vv.x), "f"(ex * vv.y),
                    "f"(ex * vv.z), "f"(ex * vv.w)
                 : "memory");
    if (lane == 0) atomicAdd(&g_sum[dst], ex);
}

// ---------------------------------------------------------------------------
// K3: out = out / (sum + 1e-16) + skip
// ---------------------------------------------------------------------------
__global__ void __launch_bounds__(256) final_kernel(float* __restrict__ out, int n) {
    int total = n * (D / 4);
    for (int t = blockIdx.x * blockDim.x + threadIdx.x; t < total;
         t += gridDim.x * blockDim.x) {
        int i = t / (D / 4);
        float r = 1.0f / (g_sum[i] + 1e-16f);
        float4 a = ((float4*)out)[t];
        float4 s = ((const float4*)g_skip)[t];
        a.x = fmaf(a.x, r, s.x);
        a.y = fmaf(a.y, r, s.y);
        a.z = fmaf(a.z, r, s.z);
        a.w = fmaf(a.w, r, s.w);
        ((float4*)out)[t] = a;
    }
}

// ---------------------------------------------------------------------------
extern "C" void kernel_launch(void* const* d_in, const int* in_sizes, int n_in,
                              void* d_out, int out_size) {
    const float* x  = (const float*)d_in[0];
    const int*   ei = (const int*)d_in[1];   // int64 in ref -> delivered int32
    // d_in[2] = edge_type (unused by reference)
    const float* Wq = (const float*)d_in[3];
    const float* bq = (const float*)d_in[4];
    const float* Wk = (const float*)d_in[5];
    const float* bk = (const float*)d_in[6];
    const float* Wv = (const float*)d_in[7];
    const float* bv = (const float*)d_in[8];
    const float* Ws = (const float*)d_in[9];
    const float* bs = (const float*)d_in[10];
    float* out = (float*)d_out;

    int n = in_sizes[0] / D;   // 100000
    int E = in_sizes[2];       // 1200000
    if (n > NN) n = NN;
    if (E > EE) E = EE;

    float *gq, *gk, *gv, *gsk;
    cudaGetSymbolAddress((void**)&gq,  g_q);
    cudaGetSymbolAddress((void**)&gk,  g_k);
    cudaGetSymbolAddress((void**)&gv,  g_v);
    cudaGetSymbolAddress((void**)&gsk, g_skip);

    // K0: init
    {
        int total  = n * D;
        int blocks = (total + 255) / 256;
        init_kernel<<<blocks, 256>>>(out, n);
    }

    // K1: fused 4-way GEMM
    {
        int blocks = (n + GR - 1) / GR;
        gemm_fused<<<blocks, 192>>>(x, Wq, bq, Wk, bk, Wv, bv, Ws, bs,
                                    gq, gk, gv, gsk, n);
    }

    // K2: fused logits + exp + scatter
    {
        long long total = (long long)E * 16;
        int blocks = (int)((total + 255) / 256);
        edge_kernel<<<blocks, 256>>>(ei, out, E);
    }

    // K3: normalize + skip
    {
        int total  = n * (D / 4);
        int blocks = (total + 255) / 256;
        final_kernel<<<blocks, 256>>>(out, n);
    }
}

// round 5
// speedup vs baseline: 2.5426x; 1.1318x over previous
#include <cuda_runtime.h>

#define NN 100000
#define EE 1200000
#define D  64
#define GR 96      // X rows per GEMM block
#define SCH 1024   // scan chunk (elements per scan block)
#define NBLK ((NN + SCH - 1) / SCH)   // 98

// Scratch (device globals: no allocation allowed in kernel_launch)
__device__ float g_q[(size_t)NN * D];
__device__ float g_k[(size_t)NN * D];
__device__ float g_v[(size_t)NN * D];
__device__ float g_skip[(size_t)NN * D];
__device__ int   g_counts[NN];
__device__ int   g_offsets[NN];
__device__ int   g_cursor[NN];
__device__ int   g_partial[128];
__device__ int   g_sorted_src[EE];

// ---------------------------------------------------------------------------
// packed f32x2 helpers (Blackwell sm_100+)
// ---------------------------------------------------------------------------
__device__ __forceinline__ unsigned long long dup_f32x2(float x) {
    unsigned long long r;
    asm("mov.b64 %0, {%1, %1};" : "=l"(r) : "f"(x));
    return r;
}
__device__ __forceinline__ void fma_f32x2(unsigned long long& acc,
                                          unsigned long long a,
                                          unsigned long long b) {
    asm("fma.rn.f32x2 %0, %1, %2, %3;" : "=l"(acc) : "l"(a), "l"(b), "l"(acc));
}
__device__ __forceinline__ float2 unpack_f32x2(unsigned long long p) {
    float lo, hi;
    asm("mov.b64 {%0, %1}, %2;" : "=f"(lo), "=f"(hi) : "l"(p));
    return make_float2(lo, hi);
}

// ---------------------------------------------------------------------------
// K1: fused 4-way GEMM: {q,k,v,skip}[n,64] = X[n,64] @ W_i[64,64] + b_i
// ---------------------------------------------------------------------------
__global__ void __launch_bounds__(192) gemm_fused(
    const float* __restrict__ X,
    const float* __restrict__ Wq, const float* __restrict__ bq,
    const float* __restrict__ Wk, const float* __restrict__ bk,
    const float* __restrict__ Wv, const float* __restrict__ bv,
    const float* __restrict__ Ws, const float* __restrict__ bs,
    float* __restrict__ Yq, float* __restrict__ Yk,
    float* __restrict__ Yv, float* __restrict__ Ys, int n) {
    __shared__ float xsT[D][GR];   // [k][row]
    __shared__ float ws[D][D];

    int tid  = threadIdx.x;
    int row0 = blockIdx.x * GR;

    for (int i = tid; i < GR * (D / 4); i += 192) {
        int r  = i % GR;
        int c4 = i / GR;
        float4 v = make_float4(0.f, 0.f, 0.f, 0.f);
        if (row0 + r < n)
            v = ((const float4*)X)[(size_t)(row0 + r) * (D / 4) + c4];
        xsT[c4 * 4 + 0][r] = v.x;
        xsT[c4 * 4 + 1][r] = v.y;
        xsT[c4 * 4 + 2][r] = v.z;
        xsT[c4 * 4 + 3][r] = v.w;
    }

    int tr = (tid >> 3) * 4;  // 0..92
    int tc = (tid & 7) * 8;   // 0..56

    const float* Wm[4] = {Wq, Wk, Wv, Ws};
    const float* Bm[4] = {bq, bk, bv, bs};
    float*       Ym[4] = {Yq, Yk, Yv, Ys};

#pragma unroll 1
    for (int w = 0; w < 4; w++) {
        __syncthreads();
        for (int i = tid; i < D * D / 4; i += 192)
            ((float4*)ws)[i] = ((const float4*)Wm[w])[i];
        __syncthreads();

        unsigned long long acc[4][4];
#pragma unroll
        for (int r = 0; r < 4; r++)
#pragma unroll
            for (int c = 0; c < 4; c++) acc[r][c] = 0ull;

#pragma unroll 8
        for (int kk = 0; kk < D; kk++) {
            float4 xv = *(const float4*)&xsT[kk][tr];
            ulonglong2 wA = *(const ulonglong2*)&ws[kk][tc];
            ulonglong2 wB = *(const ulonglong2*)&ws[kk][tc + 4];
            unsigned long long x0 = dup_f32x2(xv.x);
            unsigned long long x1 = dup_f32x2(xv.y);
            unsigned long long x2 = dup_f32x2(xv.z);
            unsigned long long x3 = dup_f32x2(xv.w);
            fma_f32x2(acc[0][0], x0, wA.x); fma_f32x2(acc[0][1], x0, wA.y);
            fma_f32x2(acc[0][2], x0, wB.x); fma_f32x2(acc[0][3], x0, wB.y);
            fma_f32x2(acc[1][0], x1, wA.x); fma_f32x2(acc[1][1], x1, wA.y);
            fma_f32x2(acc[1][2], x1, wB.x); fma_f32x2(acc[1][3], x1, wB.y);
            fma_f32x2(acc[2][0], x2, wA.x); fma_f32x2(acc[2][1], x2, wA.y);
            fma_f32x2(acc[2][2], x2, wB.x); fma_f32x2(acc[2][3], x2, wB.y);
            fma_f32x2(acc[3][0], x3, wA.x); fma_f32x2(acc[3][1], x3, wA.y);
            fma_f32x2(acc[3][2], x3, wB.x); fma_f32x2(acc[3][3], x3, wB.y);
        }

        float4 bA = ((const float4*)Bm[w])[tc / 4];
        float4 bB = ((const float4*)Bm[w])[tc / 4 + 1];
        float* Y  = Ym[w];
#pragma unroll
        for (int r = 0; r < 4; r++) {
            int grow = row0 + tr + r;
            if (grow < n) {
                float2 p0 = unpack_f32x2(acc[r][0]);
                float2 p1 = unpack_f32x2(acc[r][1]);
                float2 p2 = unpack_f32x2(acc[r][2]);
                float2 p3 = unpack_f32x2(acc[r][3]);
                float4 o0 = make_float4(p0.x + bA.x, p0.y + bA.y,
                                        p1.x + bA.z, p1.y + bA.w);
                float4 o1 = make_float4(p2.x + bB.x, p2.y + bB.y,
                                        p3.x + bB.z, p3.y + bB.w);
                ((float4*)(Y + (size_t)grow * D + tc))[0] = o0;
                ((float4*)(Y + (size_t)grow * D + tc))[1] = o1;
            }
        }
    }
}

// ---------------------------------------------------------------------------
// CSR build: histogram -> 3-phase exclusive scan -> scatter
// ---------------------------------------------------------------------------
__global__ void zero_counts(int n) {
    for (int i = blockIdx.x * blockDim.x + threadIdx.x; i < n;
         i += gridDim.x * blockDim.x)
        g_counts[i] = 0;
}

__global__ void hist_kernel(const int* __restrict__ ei, int E) {
    for (int e = blockIdx.x * blockDim.x + threadIdx.x; e < E;
         e += gridDim.x * blockDim.x)
        atomicAdd(&g_counts[ei[E + e]], 1);
}

// per-chunk exclusive scan (256 threads, 4 elems/thread)
__global__ void __launch_bounds__(256) scan1_kernel(int n) {
    __shared__ int sdata[256];
    int t    = threadIdx.x;
    int base = blockIdx.x * SCH + t * 4;

    int v[4];
#pragma unroll
    for (int j = 0; j < 4; j++)
        v[j] = (base + j < n) ? g_counts[base + j] : 0;
    int tsum = v[0] + v[1] + v[2] + v[3];

    sdata[t] = tsum;
    __syncthreads();
    for (int off = 1; off < 256; off <<= 1) {
        int x = (t >= off) ? sdata[t - off] : 0;
        __syncthreads();
        sdata[t] += x;
        __syncthreads();
    }
    int excl = sdata[t] - tsum;
    if (t == 255) g_partial[blockIdx.x] = sdata[255];

    int run = excl;
#pragma unroll
    for (int j = 0; j < 4; j++) {
        if (base + j < n) g_offsets[base + j] = run;
        run += v[j];
    }
}

__global__ void scan2_kernel(int nblk) {
    if (threadIdx.x == 0) {
        int acc = 0;
        for (int i = 0; i < nblk; i++) {
            int c = g_partial[i];
            g_partial[i] = acc;
            acc += c;
        }
    }
}

__global__ void scan3_kernel(int n) {
    for (int i = blockIdx.x * blockDim.x + threadIdx.x; i < n;
         i += gridDim.x * blockDim.x) {
        int o = g_offsets[i] + g_partial[i / SCH];
        g_offsets[i] = o;
        g_cursor[i]  = o;
    }
}

__global__ void scatter_kernel(const int* __restrict__ ei, int E) {
    for (int e = blockIdx.x * blockDim.x + threadIdx.x; e < E;
         e += gridDim.x * blockDim.x) {
        int dst = ei[E + e];
        int pos = atomicAdd(&g_cursor[dst], 1);
        g_sorted_src[pos] = ei[e];
    }
}

// ---------------------------------------------------------------------------
// K2: warp-per-destination gather. Registers hold q[dst], acc, sum.
//   out[dst] = (sum_e exp(q.k_e/8) * v_e) / (sum_e exp(...) + 1e-16) + skip[dst]
// ---------------------------------------------------------------------------
__device__ __forceinline__ float warp_sum(float d) {
#pragma unroll
    for (int o = 16; o > 0; o >>= 1)
        d += __shfl_xor_sync(0xffffffffu, d, o);
    return d;
}

__global__ void __launch_bounds__(256) gather_kernel(
    float* __restrict__ out, int n) {
    int warp = (blockIdx.x * blockDim.x + threadIdx.x) >> 5;
    int lane = threadIdx.x & 31;
    if (warp >= n) return;

    int dst = warp;
    int beg = g_offsets[dst];
    int cnt = g_counts[dst];
    int end = beg + cnt;

    float2 q2 = ((const float2*)(g_q + (size_t)dst * D))[lane];

    float2 acc = make_float2(0.f, 0.f);
    float  s   = 0.f;

    int i = beg;
    for (; i + 1 < end; i += 2) {
        int s0 = g_sorted_src[i];
        int s1 = g_sorted_src[i + 1];
        float2 k0 = ((const float2*)(g_k + (size_t)s0 * D))[lane];
        float2 k1 = ((const float2*)(g_k + (size_t)s1 * D))[lane];
        float2 v0 = ((const float2*)(g_v + (size_t)s0 * D))[lane];
        float2 v1 = ((const float2*)(g_v + (size_t)s1 * D))[lane];
        float d0 = fmaf(q2.x, k0.x, q2.y * k0.y);
        float d1 = fmaf(q2.x, k1.x, q2.y * k1.y);
#pragma unroll
        for (int o = 16; o > 0; o >>= 1) {
            d0 += __shfl_xor_sync(0xffffffffu, d0, o);
            d1 += __shfl_xor_sync(0xffffffffu, d1, o);
        }
        float ex0 = __expf(d0 * 0.125f);
        float ex1 = __expf(d1 * 0.125f);
        acc.x = fmaf(ex0, v0.x, acc.x);
        acc.y = fmaf(ex0, v0.y, acc.y);
        acc.x = fmaf(ex1, v1.x, acc.x);
        acc.y = fmaf(ex1, v1.y, acc.y);
        s += ex0 + ex1;
    }
    if (i < end) {
        int s0 = g_sorted_src[i];
        float2 k0 = ((const float2*)(g_k + (size_t)s0 * D))[lane];
        float2 v0 = ((const float2*)(g_v + (size_t)s0 * D))[lane];
        float d0 = warp_sum(fmaf(q2.x, k0.x, q2.y * k0.y));
        float ex0 = __expf(d0 * 0.125f);
        acc.x = fmaf(ex0, v0.x, acc.x);
        acc.y = fmaf(ex0, v0.y, acc.y);
        s += ex0;
    }

    float r = 1.0f / (s + 1e-16f);
    float2 sk = ((const float2*)(g_skip + (size_t)dst * D))[lane];
    float2 o;
    o.x = fmaf(acc.x, r, sk.x);
    o.y = fmaf(acc.y, r, sk.y);
    ((float2*)(out + (size_t)dst * D))[lane] = o;
}

// ---------------------------------------------------------------------------
extern "C" void kernel_launch(void* const* d_in, const int* in_sizes, int n_in,
                              void* d_out, int out_size) {
    const float* x  = (const float*)d_in[0];
    const int*   ei = (const int*)d_in[1];   // int64 in ref -> delivered int32
    // d_in[2] = edge_type (unused by reference)
    const float* Wq = (const float*)d_in[3];
    const float* bq = (const float*)d_in[4];
    const float* Wk = (const float*)d_in[5];
    const float* bk = (const float*)d_in[6];
    const float* Wv = (const float*)d_in[7];
    const float* bv = (const float*)d_in[8];
    const float* Ws = (const float*)d_in[9];
    const float* bs = (const float*)d_in[10];
    float* out = (float*)d_out;

    int n = in_sizes[0] / D;   // 100000
    int E = in_sizes[2];       // 1200000
    if (n > NN) n = NN;
    if (E > EE) E = EE;

    float *gq, *gk, *gv, *gsk;
    cudaGetSymbolAddress((void**)&gq,  g_q);
    cudaGetSymbolAddress((void**)&gk,  g_k);
    cudaGetSymbolAddress((void**)&gv,  g_v);
    cudaGetSymbolAddress((void**)&gsk, g_skip);

    int nblk = (n + SCH - 1) / SCH;

    // CSR build (independent of GEMM, overlaps via stream order anyway)
    zero_counts<<<(n + 255) / 256, 256>>>(n);
    hist_kernel<<<(E + 255) / 256, 256>>>(ei, E);
    scan1_kernel<<<nblk, 256>>>(n);
    scan2_kernel<<<1, 32>>>(nblk);
    scan3_kernel<<<(n + 255) / 256, 256>>>(n);
    scatter_kernel<<<(E + 255) / 256, 256>>>(ei, E);

    // fused 4-way GEMM
    gemm_fused<<<(n + GR - 1) / GR, 192>>>(x, Wq, bq, Wk, bk, Wv, bv, Ws, bs,
                                           gq, gk, gv, gsk, n);

    // warp-per-dst gather: attention + normalize + skip, single pass
    {
        int warps_per_block = 8;
        int blocks = (n + warps_per_block - 1) / warps_per_block;
        gather_kernel<<<blocks, 256>>>(out, n);
    }
}